// round 1
// baseline (speedup 1.0000x reference)
#include <cuda_runtime.h>
#include <cstdint>

#define BATCH 256
#define SEQ   128
#define EMBD  300
#define HID   1024
#define OUTD  20
#define CAT   1324
#define KE    304      // padded embedding K (multiple of 16)

// ---------------- scratch (static device allocations only) ----------------
__device__ float g_C[2][BATCH*HID];          // ping-pong cell state
__device__ float g_RC[BATCH*HID];            // r_t * c_prev
__device__ float g_U [BATCH*HID];            // u_t
__device__ float g_X [3L*SEQ*BATCH*HID];     // x-part pre-activations (+bias), [g][t][b][h]
__device__ float g_WRUh[2L*HID*HID];         // [W_r;W_u][:, :H]  tf32 hi
__device__ float g_WRUl[2L*HID*HID];         //                   tf32 lo
__device__ float g_WCh [1L*HID*HID];         // W_c[:, :H] hi
__device__ float g_WCl [1L*HID*HID];         //            lo
__device__ float g_WXh [3L*HID*KE];          // [W_r;W_u;W_c][:, H:] hi (K padded)
__device__ float g_WXl [3L*HID*KE];          //                       lo

// ---------------- tf32 helpers ----------------
__device__ __forceinline__ float tf32_rna(float x){
    uint32_t u;
    asm("cvt.rna.tf32.f32 %0, %1;" : "=r"(u) : "f"(x));
    return __uint_as_float(u);
}

__device__ __forceinline__ void mma_tf32(float c[4], const uint32_t a[4], const uint32_t b[2]){
    asm volatile(
      "mma.sync.aligned.m16n8k8.row.col.f32.tf32.tf32.f32 "
      "{%0,%1,%2,%3}, {%4,%5,%6,%7}, {%8,%9}, {%0,%1,%2,%3};\n"
      : "+f"(c[0]), "+f"(c[1]), "+f"(c[2]), "+f"(c[3])
      : "r"(a[0]), "r"(a[1]), "r"(a[2]), "r"(a[3]),
        "r"(b[0]), "r"(b[1]));
}

#define SMS 72                  // smem row stride (conflict-free frag loads)
#define SM_POOL (4*16*SMS)      // 4608 floats

// ---------------- generic 64x64 block GEMM (3xTF32 split) ----------------
// C[m,n] = sum_k A[m,k] * B[n,k];  B pre-split (hi/lo), A split on the fly.
// GATHER: A row m comes from emb[rows[m]] (K < EMBD guard, zero padded).
template<bool GATHER>
__device__ __forceinline__ void gemm_block(
    float* sm, const float* A, const int* rows, int lda,
    const float* Bh, const float* Bl, int ldb, int kiters,
    int m0, int n0, float acc[2][4][4])
{
    float* AH = sm;
    float* AL = sm + 16*SMS;
    float* BH = sm + 2*16*SMS;
    float* BL = sm + 3*16*SMS;
    const int tid  = threadIdx.x;
    const int lane = tid & 31;
    const int warp = tid >> 5;
    const int wm = warp >> 1, wn = warp & 1;
    const int lr = lane >> 2, lc = lane & 3;

    #pragma unroll
    for (int mt=0; mt<2; ++mt)
      #pragma unroll
      for (int nt=0; nt<4; ++nt)
        #pragma unroll
        for (int i=0;i<4;++i) acc[mt][nt][i]=0.f;

    for (int kt=0; kt<kiters; ++kt){
        const int kk = kt*16;
        // ---- A tile: 64 rows x 16 k, fp32 -> tf32 hi/lo into smem [k][m] ----
        #pragma unroll
        for (int r=0;r<2;++r){
            int idx = tid + r*128;          // 0..255 float4 slots
            int row = idx >> 2;             // 0..63
            int kq  = (idx & 3) << 2;       // 0,4,8,12
            float4 v;
            if (GATHER){
                int k = kk + kq;
                if (k < EMBD){
                    const float* ar = A + (long)rows[m0+row]*EMBD;
                    v = *reinterpret_cast<const float4*>(ar + k);
                } else {
                    v = make_float4(0.f,0.f,0.f,0.f);
                }
            } else {
                v = *reinterpret_cast<const float4*>(A + (long)(m0+row)*lda + kk + kq);
            }
            float vs[4] = {v.x,v.y,v.z,v.w};
            #pragma unroll
            for (int j=0;j<4;++j){
                float hi = tf32_rna(vs[j]);
                AH[(kq+j)*SMS + row] = hi;
                AL[(kq+j)*SMS + row] = tf32_rna(vs[j]-hi);
            }
        }
        // ---- B tile: pre-split hi/lo weights, smem [k][n] ----
        #pragma unroll
        for (int r=0;r<2;++r){
            int idx = tid + r*128;
            int row = idx >> 2;
            int kq  = (idx & 3) << 2;
            float4 vh = *reinterpret_cast<const float4*>(Bh + (long)(n0+row)*ldb + kk + kq);
            float4 vl = *reinterpret_cast<const float4*>(Bl + (long)(n0+row)*ldb + kk + kq);
            float hs[4]={vh.x,vh.y,vh.z,vh.w};
            float ls[4]={vl.x,vl.y,vl.z,vl.w};
            #pragma unroll
            for (int j=0;j<4;++j){
                BH[(kq+j)*SMS + row] = hs[j];
                BL[(kq+j)*SMS + row] = ls[j];
            }
        }
        __syncthreads();
        #pragma unroll
        for (int ks=0; ks<16; ks+=8){
            uint32_t ah[2][4], al[2][4], bh[4][2], bl[4][2];
            #pragma unroll
            for (int mt=0; mt<2; ++mt){
                int mb = wm*32 + mt*16;
                ah[mt][0] = __float_as_uint(AH[(ks+lc)*SMS   + mb     + lr]);
                ah[mt][1] = __float_as_uint(AH[(ks+lc)*SMS   + mb + 8 + lr]);
                ah[mt][2] = __float_as_uint(AH[(ks+4+lc)*SMS + mb     + lr]);
                ah[mt][3] = __float_as_uint(AH[(ks+4+lc)*SMS + mb + 8 + lr]);
                al[mt][0] = __float_as_uint(AL[(ks+lc)*SMS   + mb     + lr]);
                al[mt][1] = __float_as_uint(AL[(ks+lc)*SMS   + mb + 8 + lr]);
                al[mt][2] = __float_as_uint(AL[(ks+4+lc)*SMS + mb     + lr]);
                al[mt][3] = __float_as_uint(AL[(ks+4+lc)*SMS + mb + 8 + lr]);
            }
            #pragma unroll
            for (int nt=0; nt<4; ++nt){
                int nb = wn*32 + nt*8;
                bh[nt][0] = __float_as_uint(BH[(ks+lc)*SMS   + nb + lr]);
                bh[nt][1] = __float_as_uint(BH[(ks+4+lc)*SMS + nb + lr]);
                bl[nt][0] = __float_as_uint(BL[(ks+lc)*SMS   + nb + lr]);
                bl[nt][1] = __float_as_uint(BL[(ks+4+lc)*SMS + nb + lr]);
            }
            #pragma unroll
            for (int mt=0; mt<2; ++mt)
              #pragma unroll
              for (int nt=0; nt<4; ++nt){
                mma_tf32(acc[mt][nt], ah[mt], bh[nt]);   // hi*hi
                mma_tf32(acc[mt][nt], al[mt], bh[nt]);   // lo*hi
                mma_tf32(acc[mt][nt], ah[mt], bl[nt]);   // hi*lo
              }
        }
        __syncthreads();
    }
}

// ---------------- weight preprocessing: pack + tf32 split ----------------
__global__ void k_prep(const float* __restrict__ Wr, const float* __restrict__ Wu,
                       const float* __restrict__ Wc)
{
    const long N1 = 2L*HID*HID;
    const long N2 = 1L*HID*HID;
    const long N3 = 3L*HID*KE;
    const long total = N1+N2+N3;
    for (long i = blockIdx.x*(long)blockDim.x + threadIdx.x; i < total;
         i += (long)gridDim.x*blockDim.x){
        float v; float *dh, *dl; long j;
        if (i < N1){
            j = i; int n = (int)(j/HID), k = (int)(j - (long)n*HID);
            v = (n < HID) ? Wr[(long)n*CAT + k] : Wu[(long)(n-HID)*CAT + k];
            dh = g_WRUh; dl = g_WRUl;
        } else if (i < N1+N2){
            j = i - N1; int n = (int)(j/HID), k = (int)(j - (long)n*HID);
            v = Wc[(long)n*CAT + k];
            dh = g_WCh; dl = g_WCl;
        } else {
            j = i - N1 - N2; int n = (int)(j/KE), k = (int)(j - (long)n*KE);
            int g = n / HID, h = n - g*HID;
            const float* W = (g==0) ? Wr : ((g==1) ? Wu : Wc);
            v = (k < EMBD) ? W[(long)h*CAT + HID + k] : 0.0f;
            dh = g_WXh; dl = g_WXl;
        }
        float hi = tf32_rna(v);
        dh[j] = hi;
        dl[j] = tf32_rna(v - hi);
    }
}

// ---------------- init: zero state, preload output with b_p ----------------
__global__ void k_init(float* __restrict__ out, const float* __restrict__ bp){
    const long n_out = (long)BATCH*SEQ*OUTD;
    for (long i = blockIdx.x*(long)blockDim.x + threadIdx.x; i < n_out;
         i += (long)gridDim.x*blockDim.x){
        out[i] = bp[i % OUTD];
        if (i < (long)BATCH*HID) g_C[0][i] = 0.f;
    }
}

// ---------------- x-part GEMM: [32768,300] x [300,3072] (+bias) ----------------
__global__ void __launch_bounds__(128) k_xgemm(const int* __restrict__ x,
        const float* __restrict__ emb,
        const float* __restrict__ br, const float* __restrict__ bu,
        const float* __restrict__ bc)
{
    __shared__ float sm[SM_POOL];
    float acc[2][4][4];
    const int m0 = blockIdx.x*64, n0 = blockIdx.y*64;
    gemm_block<true>(sm, emb, x, EMBD, g_WXh, g_WXl, KE, KE/16, m0, n0, acc);
    const int lane = threadIdx.x & 31, warp = threadIdx.x >> 5;
    const int wm = warp>>1, wn = warp&1;
    const int g = n0 >> 10;                       // gate: block-uniform
    const float* bias = (g==0)?br:((g==1)?bu:bc);
    #pragma unroll
    for (int mt=0; mt<2; ++mt){
      #pragma unroll
      for (int nt=0; nt<4; ++nt){
        const int r0 = m0 + wm*32 + mt*16 + (lane>>2);
        const int c0 = n0 + wn*32 + nt*8 + (lane&3)*2;
        #pragma unroll
        for (int e=0;e<4;++e){
            const int m = r0 + (e>>1)*8;
            const int n = c0 + (e&1);
            const int b = m >> 7, t = m & (SEQ-1);
            const int h = n & (HID-1);
            g_X[(((long)g*SEQ + t)*BATCH + b)*HID + h] = acc[mt][nt][e] + bias[h];
        }
      }
    }
}

// ---------------- step A: gates r,u (fused GEMM 256x2048) ----------------
__global__ void __launch_bounds__(128) k_stepA(int t){
    __shared__ float sm[SM_POOL];
    float acc[2][4][4];
    const float* cprev = g_C[t&1];
    const int m0 = blockIdx.x*64, n0 = blockIdx.y*64;
    gemm_block<false>(sm, cprev, nullptr, HID, g_WRUh, g_WRUl, HID, HID/16, m0, n0, acc);
    const int lane = threadIdx.x & 31, warp = threadIdx.x >> 5;
    const int wm = warp>>1, wn = warp&1;
    const bool isU = (n0 >= HID);                 // block-uniform
    const long xbase = (((long)(isU?1:0)*SEQ + t)*BATCH)*HID;
    #pragma unroll
    for (int mt=0; mt<2; ++mt){
      #pragma unroll
      for (int nt=0; nt<4; ++nt){
        const int r0 = m0 + wm*32 + mt*16 + (lane>>2);
        const int c0 = n0 + wn*32 + nt*8 + (lane&3)*2;
        #pragma unroll
        for (int e=0;e<4;++e){
            const int b = r0 + (e>>1)*8;
            const int n = c0 + (e&1);
            const int h = n & (HID-1);
            const float pre = acc[mt][nt][e] + g_X[xbase + (long)b*HID + h];
            const float s = 1.f/(1.f+expf(-pre));
            if (isU) g_U[b*HID+h]  = s;
            else     g_RC[b*HID+h] = s * cprev[b*HID+h];
        }
      }
    }
}

// ---------------- step B: candidate GEMM + state update + y-projection ----------------
__global__ void __launch_bounds__(128) k_stepB(int t, const float* __restrict__ Wp,
                                               float* __restrict__ out){
    __shared__ float sm[SM_POOL + 20*68];
    float acc[2][4][4];
    const float* cprev = g_C[t&1];
    float* cnext = g_C[(t+1)&1];
    const int m0 = blockIdx.x*64, n0 = blockIdx.y*64;
    gemm_block<false>(sm, g_RC, nullptr, HID, g_WCh, g_WCl, HID, HID/16, m0, n0, acc);

    float* Cs  = sm;             // 64 x 68, reuses mainloop smem (safe after final sync)
    float* Wps = sm + SM_POOL;   // 20 x 68
    const int tid = threadIdx.x;
    for (int i = tid; i < 20*64; i += 128){
        const int o = i >> 6, hh = i & 63;
        Wps[o*68 + hh] = Wp[(long)o*HID + n0 + hh];
    }
    const int lane = tid & 31, warp = tid >> 5;
    const int wm = warp>>1, wn = warp&1;
    const long xbase = ((2L*SEQ + t)*BATCH)*HID;
    #pragma unroll
    for (int mt=0; mt<2; ++mt){
      #pragma unroll
      for (int nt=0; nt<4; ++nt){
        const int r0 = m0 + wm*32 + mt*16 + (lane>>2);
        const int c0 = n0 + wn*32 + nt*8 + (lane&3)*2;
        #pragma unroll
        for (int e=0;e<4;++e){
            const int b = r0 + (e>>1)*8;
            const int h = c0 + (e&1);
            const float cc = tanhf(acc[mt][nt][e] + g_X[xbase + (long)b*HID + h]);
            const float u  = g_U[b*HID+h];
            const float cp = cprev[b*HID+h];
            const float cn = u*cc + (1.f-u)*cp;
            cnext[b*HID+h] = cn;
            Cs[(b - m0)*68 + (h - n0)] = cn;
        }
      }
    }
    __syncthreads();
    // partial y for this h-chunk: 128 threads -> (64 rows) x (2 groups of 10 outputs)
    const int ml = tid & 63, og = tid >> 6;
    float s[10];
    #pragma unroll
    for (int j=0;j<10;++j) s[j]=0.f;
    for (int hh=0; hh<64; ++hh){
        const float c = Cs[ml*68 + hh];
        #pragma unroll
        for (int j=0;j<10;++j) s[j] += c * Wps[(og*10+j)*68 + hh];
    }
    const int b = m0 + ml;
    #pragma unroll
    for (int j=0;j<10;++j)
        atomicAdd(&out[((long)b*SEQ + t)*OUTD + og*10 + j], s[j]);
}

// ---------------- launch ----------------
extern "C" void kernel_launch(void* const* d_in, const int* in_sizes, int n_in,
                              void* d_out, int out_size){
    const int*   x   = (const int*)  d_in[0];
    const float* emb = (const float*)d_in[1];
    const float* Wr  = (const float*)d_in[2];
    const float* br  = (const float*)d_in[3];
    const float* Wu  = (const float*)d_in[4];
    const float* bu  = (const float*)d_in[5];
    const float* Wc  = (const float*)d_in[6];
    const float* bc  = (const float*)d_in[7];
    const float* Wp  = (const float*)d_in[8];
    const float* bp  = (const float*)d_in[9];
    float* out = (float*)d_out;
    (void)in_sizes; (void)n_in; (void)out_size;

    k_init<<<512, 256>>>(out, bp);
    k_prep<<<1024, 256>>>(Wr, Wu, Wc);
    k_xgemm<<<dim3(512,48), 128>>>(x, emb, br, bu, bc);
    for (int t=0; t<SEQ; ++t){
        k_stepA<<<dim3(4,32), 128>>>(t);
        k_stepB<<<dim3(4,16), 128>>>(t, Wp, out);
    }
}

// round 2
// speedup vs baseline: 1.4484x; 1.4484x over previous
#include <cuda_runtime.h>
#include <cstdint>

#define BATCH 256
#define SEQ   128
#define EMBD  300
#define HID   1024
#define OUTD  20
#define CAT   1324
#define KE    304      // padded embedding K (multiple of 16)

// ---------------- scratch (static device allocations only) ----------------
__device__ float g_C[2][BATCH*HID];          // ping-pong cell state
__device__ float g_RC[BATCH*HID];            // r_t * c_prev
__device__ float g_U [BATCH*HID];            // u_t
__device__ float g_X [3L*SEQ*BATCH*HID];     // x-part pre-activations (+bias), [g][t][b][h]
__device__ float g_WRUh[2L*HID*HID];         // [W_r;W_u][:, :H]  tf32 hi
__device__ float g_WRUl[2L*HID*HID];         //                   tf32 lo
__device__ float g_WCh [1L*HID*HID];         // W_c[:, :H] hi
__device__ float g_WCl [1L*HID*HID];         //            lo
__device__ float g_WXh [3L*HID*KE];          // [W_r;W_u;W_c][:, H:] hi (K padded)
__device__ float g_WXl [3L*HID*KE];          //                       lo

// ---------------- tf32 helpers ----------------
__device__ __forceinline__ float tf32_rna(float x){
    uint32_t u;
    asm("cvt.rna.tf32.f32 %0, %1;" : "=r"(u) : "f"(x));
    return __uint_as_float(u);
}

__device__ __forceinline__ void mma_tf32(float c[4], const uint32_t a[4], const uint32_t b[2]){
    asm volatile(
      "mma.sync.aligned.m16n8k8.row.col.f32.tf32.tf32.f32 "
      "{%0,%1,%2,%3}, {%4,%5,%6,%7}, {%8,%9}, {%0,%1,%2,%3};\n"
      : "+f"(c[0]), "+f"(c[1]), "+f"(c[2]), "+f"(c[3])
      : "r"(a[0]), "r"(a[1]), "r"(a[2]), "r"(a[3]),
        "r"(b[0]), "r"(b[1]));
}

#define SMS 72                  // smem row stride (conflict-free frag loads)
#define SM_POOL (4*16*SMS)      // 4608 floats

// ---------------- generic 64x64 block GEMM (3xTF32 split) ----------------
// C[m,n] = sum_k A[m,k] * B[n,k];  B pre-split (hi/lo), A split on the fly.
// GATHER: A row m comes from emb[rows[m]] (K < EMBD guard, zero padded).
template<bool GATHER>
__device__ __forceinline__ void gemm_block(
    float* sm, const float* A, const int* rows, int lda,
    const float* Bh, const float* Bl, int ldb, int kiters,
    int m0, int n0, float acc[2][4][4])
{
    float* AH = sm;
    float* AL = sm + 16*SMS;
    float* BH = sm + 2*16*SMS;
    float* BL = sm + 3*16*SMS;
    const int tid  = threadIdx.x;
    const int lane = tid & 31;
    const int warp = tid >> 5;
    const int wm = warp >> 1, wn = warp & 1;
    const int lr = lane >> 2, lc = lane & 3;

    #pragma unroll
    for (int mt=0; mt<2; ++mt)
      #pragma unroll
      for (int nt=0; nt<4; ++nt)
        #pragma unroll
        for (int i=0;i<4;++i) acc[mt][nt][i]=0.f;

    for (int kt=0; kt<kiters; ++kt){
        const int kk = kt*16;
        // ---- A tile: 64 rows x 16 k, fp32 -> tf32 hi/lo into smem [k][m] ----
        #pragma unroll
        for (int r=0;r<2;++r){
            int idx = tid + r*128;          // 0..255 float4 slots
            int row = idx >> 2;             // 0..63
            int kq  = (idx & 3) << 2;       // 0,4,8,12
            float4 v;
            if (GATHER){
                int k = kk + kq;
                if (k < EMBD){
                    const float* ar = A + (long)rows[m0+row]*EMBD;
                    v = *reinterpret_cast<const float4*>(ar + k);
                } else {
                    v = make_float4(0.f,0.f,0.f,0.f);
                }
            } else {
                v = *reinterpret_cast<const float4*>(A + (long)(m0+row)*lda + kk + kq);
            }
            float vs[4] = {v.x,v.y,v.z,v.w};
            #pragma unroll
            for (int j=0;j<4;++j){
                float hi = tf32_rna(vs[j]);
                AH[(kq+j)*SMS + row] = hi;
                AL[(kq+j)*SMS + row] = tf32_rna(vs[j]-hi);
            }
        }
        // ---- B tile: pre-split hi/lo weights, smem [k][n] ----
        #pragma unroll
        for (int r=0;r<2;++r){
            int idx = tid + r*128;
            int row = idx >> 2;
            int kq  = (idx & 3) << 2;
            float4 vh = *reinterpret_cast<const float4*>(Bh + (long)(n0+row)*ldb + kk + kq);
            float4 vl = *reinterpret_cast<const float4*>(Bl + (long)(n0+row)*ldb + kk + kq);
            float hs[4]={vh.x,vh.y,vh.z,vh.w};
            float ls[4]={vl.x,vl.y,vl.z,vl.w};
            #pragma unroll
            for (int j=0;j<4;++j){
                BH[(kq+j)*SMS + row] = hs[j];
                BL[(kq+j)*SMS + row] = ls[j];
            }
        }
        __syncthreads();
        #pragma unroll
        for (int ks=0; ks<16; ks+=8){
            uint32_t ah[2][4], al[2][4], bh[4][2], bl[4][2];
            #pragma unroll
            for (int mt=0; mt<2; ++mt){
                int mb = wm*32 + mt*16;
                ah[mt][0] = __float_as_uint(AH[(ks+lc)*SMS   + mb     + lr]);
                ah[mt][1] = __float_as_uint(AH[(ks+lc)*SMS   + mb + 8 + lr]);
                ah[mt][2] = __float_as_uint(AH[(ks+4+lc)*SMS + mb     + lr]);
                ah[mt][3] = __float_as_uint(AH[(ks+4+lc)*SMS + mb + 8 + lr]);
                al[mt][0] = __float_as_uint(AL[(ks+lc)*SMS   + mb     + lr]);
                al[mt][1] = __float_as_uint(AL[(ks+lc)*SMS   + mb + 8 + lr]);
                al[mt][2] = __float_as_uint(AL[(ks+4+lc)*SMS + mb     + lr]);
                al[mt][3] = __float_as_uint(AL[(ks+4+lc)*SMS + mb + 8 + lr]);
            }
            #pragma unroll
            for (int nt=0; nt<4; ++nt){
                int nb = wn*32 + nt*8;
                bh[nt][0] = __float_as_uint(BH[(ks+lc)*SMS   + nb + lr]);
                bh[nt][1] = __float_as_uint(BH[(ks+4+lc)*SMS + nb + lr]);
                bl[nt][0] = __float_as_uint(BL[(ks+lc)*SMS   + nb + lr]);
                bl[nt][1] = __float_as_uint(BL[(ks+4+lc)*SMS + nb + lr]);
            }
            #pragma unroll
            for (int mt=0; mt<2; ++mt)
              #pragma unroll
              for (int nt=0; nt<4; ++nt){
                mma_tf32(acc[mt][nt], ah[mt], bh[nt]);   // hi*hi
                mma_tf32(acc[mt][nt], al[mt], bh[nt]);   // lo*hi
                mma_tf32(acc[mt][nt], ah[mt], bl[nt]);   // hi*lo
              }
        }
        __syncthreads();
    }
}

// ---------------- weight preprocessing: pack + tf32 split ----------------
__global__ void k_prep(const float* __restrict__ Wr, const float* __restrict__ Wu,
                       const float* __restrict__ Wc)
{
    const long N1 = 2L*HID*HID;
    const long N2 = 1L*HID*HID;
    const long N3 = 3L*HID*KE;
    const long total = N1+N2+N3;
    for (long i = blockIdx.x*(long)blockDim.x + threadIdx.x; i < total;
         i += (long)gridDim.x*blockDim.x){
        float v; float *dh, *dl; long j;
        if (i < N1){
            j = i; int n = (int)(j/HID), k = (int)(j - (long)n*HID);
            v = (n < HID) ? Wr[(long)n*CAT + k] : Wu[(long)(n-HID)*CAT + k];
            dh = g_WRUh; dl = g_WRUl;
        } else if (i < N1+N2){
            j = i - N1; int n = (int)(j/HID), k = (int)(j - (long)n*HID);
            v = Wc[(long)n*CAT + k];
            dh = g_WCh; dl = g_WCl;
        } else {
            j = i - N1 - N2; int n = (int)(j/KE), k = (int)(j - (long)n*KE);
            int g = n / HID, h = n - g*HID;
            const float* W = (g==0) ? Wr : ((g==1) ? Wu : Wc);
            v = (k < EMBD) ? W[(long)h*CAT + HID + k] : 0.0f;
            dh = g_WXh; dl = g_WXl;
        }
        float hi = tf32_rna(v);
        dh[j] = hi;
        dl[j] = tf32_rna(v - hi);
    }
}

// ---------------- init: zero state, preload output with b_p ----------------
__global__ void k_init(float* __restrict__ out, const float* __restrict__ bp){
    const long n_out = (long)BATCH*SEQ*OUTD;
    for (long i = blockIdx.x*(long)blockDim.x + threadIdx.x; i < n_out;
         i += (long)gridDim.x*blockDim.x){
        out[i] = bp[i % OUTD];
        if (i < (long)BATCH*HID) g_C[0][i] = 0.f;
    }
}

// ---------------- x-part GEMM: [32768,300] x [300,3072] (+bias) ----------------
__global__ void __launch_bounds__(128) k_xgemm(const int* __restrict__ x,
        const float* __restrict__ emb,
        const float* __restrict__ br, const float* __restrict__ bu,
        const float* __restrict__ bc)
{
    __shared__ float sm[SM_POOL];
    float acc[2][4][4];
    const int m0 = blockIdx.x*64, n0 = blockIdx.y*64;
    gemm_block<true>(sm, emb, x, EMBD, g_WXh, g_WXl, KE, KE/16, m0, n0, acc);
    const int lane = threadIdx.x & 31, warp = threadIdx.x >> 5;
    const int wm = warp>>1, wn = warp&1;
    const int g = n0 >> 10;                       // gate: block-uniform
    const float* bias = (g==0)?br:((g==1)?bu:bc);
    #pragma unroll
    for (int mt=0; mt<2; ++mt){
      #pragma unroll
      for (int nt=0; nt<4; ++nt){
        const int r0 = m0 + wm*32 + mt*16 + (lane>>2);
        const int c0 = n0 + wn*32 + nt*8 + (lane&3)*2;
        #pragma unroll
        for (int e=0;e<4;++e){
            const int m = r0 + (e>>1)*8;
            const int n = c0 + (e&1);
            const int b = m >> 7, t = m & (SEQ-1);
            const int h = n & (HID-1);
            g_X[(((long)g*SEQ + t)*BATCH + b)*HID + h] = acc[mt][nt][e] + bias[h];
        }
      }
    }
}

// ---------------- step A: gates r,u (fused GEMM 256x2048) ----------------
__global__ void __launch_bounds__(128) k_stepA(int t){
    __shared__ float sm[SM_POOL];
    float acc[2][4][4];
    const float* cprev = g_C[t&1];
    const int m0 = blockIdx.x*64, n0 = blockIdx.y*64;
    gemm_block<false>(sm, cprev, nullptr, HID, g_WRUh, g_WRUl, HID, HID/16, m0, n0, acc);
    const int lane = threadIdx.x & 31, warp = threadIdx.x >> 5;
    const int wm = warp>>1, wn = warp&1;
    const bool isU = (n0 >= HID);                 // block-uniform
    const long xbase = (((long)(isU?1:0)*SEQ + t)*BATCH)*HID;
    #pragma unroll
    for (int mt=0; mt<2; ++mt){
      #pragma unroll
      for (int nt=0; nt<4; ++nt){
        const int r0 = m0 + wm*32 + mt*16 + (lane>>2);
        const int c0 = n0 + wn*32 + nt*8 + (lane&3)*2;
        #pragma unroll
        for (int e=0;e<4;++e){
            const int b = r0 + (e>>1)*8;
            const int n = c0 + (e&1);
            const int h = n & (HID-1);
            const float pre = acc[mt][nt][e] + g_X[xbase + (long)b*HID + h];
            const float s = 1.f/(1.f+expf(-pre));
            if (isU) g_U[b*HID+h]  = s;
            else     g_RC[b*HID+h] = s * cprev[b*HID+h];
        }
      }
    }
}

// ---------------- step B: candidate GEMM + state update + y-projection ----------------
__global__ void __launch_bounds__(128) k_stepB(int t, const float* __restrict__ Wp,
                                               float* __restrict__ out){
    __shared__ float sm[SM_POOL + 20*68];
    float acc[2][4][4];
    const float* cprev = g_C[t&1];
    float* cnext = g_C[(t+1)&1];
    const int m0 = blockIdx.x*64, n0 = blockIdx.y*64;
    gemm_block<false>(sm, g_RC, nullptr, HID, g_WCh, g_WCl, HID, HID/16, m0, n0, acc);

    float* Cs  = sm;             // 64 x 68, reuses mainloop smem (safe after final sync)
    float* Wps = sm + SM_POOL;   // 20 x 68
    const int tid = threadIdx.x;
    for (int i = tid; i < 20*64; i += 128){
        const int o = i >> 6, hh = i & 63;
        Wps[o*68 + hh] = Wp[(long)o*HID + n0 + hh];
    }
    const int lane = tid & 31, warp = tid >> 5;
    const int wm = warp>>1, wn = warp&1;
    const long xbase = ((2L*SEQ + t)*BATCH)*HID;
    #pragma unroll
    for (int mt=0; mt<2; ++mt){
      #pragma unroll
      for (int nt=0; nt<4; ++nt){
        const int r0 = m0 + wm*32 + mt*16 + (lane>>2);
        const int c0 = n0 + wn*32 + nt*8 + (lane&3)*2;
        #pragma unroll
        for (int e=0;e<4;++e){
            const int b = r0 + (e>>1)*8;
            const int h = c0 + (e&1);
            const float cc = tanhf(acc[mt][nt][e] + g_X[xbase + (long)b*HID + h]);
            const float u  = g_U[b*HID+h];
            const float cp = cprev[b*HID+h];
            const float cn = u*cc + (1.f-u)*cp;
            cnext[b*HID+h] = cn;
            Cs[(b - m0)*68 + (h - n0)] = cn;
        }
      }
    }
    __syncthreads();
    // partial y for this h-chunk: 128 threads -> (64 rows) x (2 groups of 10 outputs)
    const int ml = tid & 63, og = tid >> 6;
    float s[10];
    #pragma unroll
    for (int j=0;j<10;++j) s[j]=0.f;
    for (int hh=0; hh<64; ++hh){
        const float c = Cs[ml*68 + hh];
        #pragma unroll
        for (int j=0;j<10;++j) s[j] += c * Wps[(og*10+j)*68 + hh];
    }
    const int b = m0 + ml;
    #pragma unroll
    for (int j=0;j<10;++j)
        atomicAdd(&out[((long)b*SEQ + t)*OUTD + og*10 + j], s[j]);
}

// ---------------- launch ----------------
extern "C" void kernel_launch(void* const* d_in, const int* in_sizes, int n_in,
                              void* d_out, int out_size){
    const int*   x   = (const int*)  d_in[0];
    const float* emb = (const float*)d_in[1];
    const float* Wr  = (const float*)d_in[2];
    const float* br  = (const float*)d_in[3];
    const float* Wu  = (const float*)d_in[4];
    const float* bu  = (const float*)d_in[5];
    const float* Wc  = (const float*)d_in[6];
    const float* bc  = (const float*)d_in[7];
    const float* Wp  = (const float*)d_in[8];
    const float* bp  = (const float*)d_in[9];
    float* out = (float*)d_out;
    (void)in_sizes; (void)n_in; (void)out_size;

    k_init<<<512, 256>>>(out, bp);
    k_prep<<<1024, 256>>>(Wr, Wu, Wc);
    k_xgemm<<<dim3(512,48), 128>>>(x, emb, br, bu, bc);
    for (int t=0; t<SEQ; ++t){
        k_stepA<<<dim3(4,32), 128>>>(t);
        k_stepB<<<dim3(4,16), 128>>>(t, Wp, out);
    }
}

// round 5
// speedup vs baseline: 2.8421x; 1.9622x over previous
#include <cuda_runtime.h>
#include <cstdint>

#define BATCH 256
#define SEQ   128
#define HID   1024
#define EMBD  300
#define OUTD  20
#define CAT   1324
#define KE    304
#define NROWS 32768
#define PCTA  128

// ---------------- static device scratch (all fp32) ----------------
__device__ float g_c32[BATCH*HID];                  // full-precision cell state
__device__ float g_Ch [BATCH*HID], g_Cl [BATCH*HID];   // tf32 hi/lo of c
__device__ float g_RCh[BATCH*HID], g_RCl[BATCH*HID];   // tf32 hi/lo of r*c
__device__ float g_u  [BATCH*HID];
__device__ float g_X  [3L*SEQ*BATCH*HID];           // x-part preacts (+bias) [g][t][b][h]
__device__ float g_Wruh[2048L*HID], g_Wrul[2048L*HID];
__device__ float g_Wch [1024L*HID], g_Wcl [1024L*HID];
__device__ float g_Wxh [3L*HID*KE], g_Wxl [3L*HID*KE];
__device__ float g_xeh [(long)NROWS*KE], g_xel[(long)NROWS*KE];
__device__ unsigned g_barcnt;

// ---------------- tf32 helpers (validated in R1) ----------------
__device__ __forceinline__ float tf32_rna(float x){
    uint32_t u;
    asm("cvt.rna.tf32.f32 %0, %1;" : "=r"(u) : "f"(x));
    return __uint_as_float(u);
}
__device__ __forceinline__ void mma_tf32(float c[4], const uint32_t a[4], const uint32_t b[2]){
    asm volatile(
      "mma.sync.aligned.m16n8k8.row.col.f32.tf32.tf32.f32 "
      "{%0,%1,%2,%3}, {%4,%5,%6,%7}, {%8,%9}, {%0,%1,%2,%3};\n"
      : "+f"(c[0]), "+f"(c[1]), "+f"(c[2]), "+f"(c[3])
      : "r"(a[0]), "r"(a[1]), "r"(a[2]), "r"(a[3]),
        "r"(b[0]), "r"(b[1]));
}
__device__ __forceinline__ void cp16(uint32_t d, const void* s){
    asm volatile("cp.async.cg.shared.global [%0], [%1], 16;" :: "r"(d), "l"(s));
}
#define CP_COMMIT asm volatile("cp.async.commit_group;")
#define CP_WAIT1  asm volatile("cp.async.wait_group 1;")

#define S20 20   // smem row stride (floats): 16 data + 4 pad -> conflict-free frag LDS

// ---------------- GEMM core: (MT*32) x 64 tile, K chunks of 16, 8 warps 2x4 ----
// C[m,n] = sum_k A[m,k]*B[n,k]; A,B pre-split tf32 hi/lo fp32 arrays in global.
// Row-major smem, 3-stage cp.async pipeline. Fragment math identical to R1.
template<int MT>
__device__ void gemm32(char* sm,
    const float* __restrict__ Ah, const float* __restrict__ Al, int lda,
    const float* __restrict__ Bh, const float* __restrict__ Bl, int ldb,
    int m0, int n0, int K, float acc[MT][2][4])
{
    constexpr int AR   = MT*32;
    constexpr int OAL  = AR*S20;            // float offsets within stage
    constexpr int OBH  = 2*AR*S20;
    constexpr int OBL  = 2*AR*S20 + 64*S20;
    constexpr int STGf = 2*AR*S20 + 2*64*S20;
    const int tid = threadIdx.x, lane = tid&31, warp = tid>>5;
    const int wm = warp>>2, wn = warp&3;
    const int lr = lane>>2, lc = lane&3;
    uint32_t smb = (uint32_t)__cvta_generic_to_shared(sm);
    float* smf = (float*)sm;

    #pragma unroll
    for (int i=0;i<MT;i++)
      #pragma unroll
      for (int j=0;j<2;j++)
        #pragma unroll
        for (int e=0;e<4;e++) acc[i][j][e]=0.f;

    auto fill = [&](int ki, int buf){
        const int kk = ki*16;
        const uint32_t pb = smb + (uint32_t)buf*STGf*4;
        for (int idx = tid; idx < AR*4; idx += 256){
            int r = idx>>2, c = idx&3;
            size_t off = (size_t)(m0+r)*lda + kk + c*4;
            cp16(pb + (uint32_t)(r*S20 + c*4)*4,       Ah + off);
            cp16(pb + (uint32_t)(OAL + r*S20 + c*4)*4, Al + off);
        }
        for (int idx = tid; idx < 64*4; idx += 256){
            int r = idx>>2, c = idx&3;
            size_t off = (size_t)(n0+r)*ldb + kk + c*4;
            cp16(pb + (uint32_t)(OBH + r*S20 + c*4)*4, Bh + off);
            cp16(pb + (uint32_t)(OBL + r*S20 + c*4)*4, Bl + off);
        }
    };

    const int nk = K/16;
    fill(0,0); CP_COMMIT;
    fill(1,1); CP_COMMIT;

    for (int i=0;i<nk;i++){
        CP_WAIT1;
        __syncthreads();
        if (i+2 < nk) fill(i+2, (i+2)%3);
        CP_COMMIT;
        const float* p = smf + (i%3)*STGf;
        #pragma unroll
        for (int ks=0; ks<16; ks+=8){
            uint32_t ah[MT][4], al[MT][4], bh[2][2], bl[2][2];
            #pragma unroll
            for (int mt=0; mt<MT; mt++){
                const int R = wm*MT*16 + mt*16;
                ah[mt][0] = __float_as_uint(p[(R+lr)*S20   + ks+lc]);
                ah[mt][1] = __float_as_uint(p[(R+8+lr)*S20 + ks+lc]);
                ah[mt][2] = __float_as_uint(p[(R+lr)*S20   + ks+4+lc]);
                ah[mt][3] = __float_as_uint(p[(R+8+lr)*S20 + ks+4+lc]);
                al[mt][0] = __float_as_uint(p[OAL + (R+lr)*S20   + ks+lc]);
                al[mt][1] = __float_as_uint(p[OAL + (R+8+lr)*S20 + ks+lc]);
                al[mt][2] = __float_as_uint(p[OAL + (R+lr)*S20   + ks+4+lc]);
                al[mt][3] = __float_as_uint(p[OAL + (R+8+lr)*S20 + ks+4+lc]);
            }
            #pragma unroll
            for (int nt=0; nt<2; nt++){
                const int N = wn*16 + nt*8;
                bh[nt][0] = __float_as_uint(p[OBH + (N+lr)*S20 + ks+lc]);
                bh[nt][1] = __float_as_uint(p[OBH + (N+lr)*S20 + ks+4+lc]);
                bl[nt][0] = __float_as_uint(p[OBL + (N+lr)*S20 + ks+lc]);
                bl[nt][1] = __float_as_uint(p[OBL + (N+lr)*S20 + ks+4+lc]);
            }
            #pragma unroll
            for (int mt=0; mt<MT; mt++)
              #pragma unroll
              for (int nt=0; nt<2; nt++){
                  mma_tf32(acc[mt][nt], ah[mt], bh[nt]);   // hi*hi
                  mma_tf32(acc[mt][nt], al[mt], bh[nt]);   // lo*hi
                  mma_tf32(acc[mt][nt], ah[mt], bl[nt]);   // hi*lo
              }
        }
        __syncthreads();
    }
}

// ---------------- grid barrier (release/acquire, monotonic counter) -----------
__device__ __forceinline__ void gridbar(unsigned& nbar){
    __threadfence();
    __syncthreads();
    ++nbar;
    if (threadIdx.x == 0){
        asm volatile("red.release.gpu.global.add.u32 [%0], 1;" :: "l"(&g_barcnt) : "memory");
        const unsigned target = (unsigned)PCTA * nbar;
        unsigned v;
        do {
            asm volatile("ld.acquire.gpu.global.u32 %0, [%1];" : "=r"(v) : "l"(&g_barcnt) : "memory");
        } while (v < target);
    }
    __syncthreads();
}

// ---------------- prep kernels ----------------
__global__ void k_init(float* __restrict__ out, const float* __restrict__ bp){
    const long nout = (long)BATCH*SEQ*OUTD;
    for (long i = blockIdx.x*(long)blockDim.x + threadIdx.x; i < nout;
         i += (long)gridDim.x*blockDim.x){
        out[i] = bp[i % OUTD];
        if (i < (long)BATCH*HID){
            g_c32[i] = 0.f; g_Ch[i] = 0.f; g_Cl[i] = 0.f;
        }
        if (i == 0) g_barcnt = 0u;
    }
}

__global__ void k_prep(const float* __restrict__ Wr, const float* __restrict__ Wu,
                       const float* __restrict__ Wc){
    const long N1 = 2048L*HID, N2 = 1024L*HID, N3 = 3L*HID*KE;
    for (long i = blockIdx.x*(long)blockDim.x + threadIdx.x; i < N1+N2+N3;
         i += (long)gridDim.x*blockDim.x){
        float v; float *dh, *dl; long j;
        if (i < N1){
            j = i; int n = (int)(j/HID), k = (int)(j - (long)n*HID);
            v = (n < 1024) ? Wr[(long)n*CAT + k] : Wu[(long)(n-1024)*CAT + k];
            dh = g_Wruh; dl = g_Wrul;
        } else if (i < N1+N2){
            j = i - N1; int n = (int)(j/HID), k = (int)(j - (long)n*HID);
            v = Wc[(long)n*CAT + k];
            dh = g_Wch; dl = g_Wcl;
        } else {
            j = i - N1 - N2; int n = (int)(j/KE), k = (int)(j - (long)n*KE);
            int g = n / HID, h = n - g*HID;
            const float* W = (g==0)?Wr:((g==1)?Wu:Wc);
            v = (k < EMBD) ? W[(long)h*CAT + HID + k] : 0.f;
            dh = g_Wxh; dl = g_Wxl;
        }
        float hi = tf32_rna(v);
        dh[j] = hi; dl[j] = tf32_rna(v - hi);
    }
}

__global__ void k_gather(const int* __restrict__ x, const float* __restrict__ emb){
    const long total = (long)NROWS*KE;
    for (long i = blockIdx.x*(long)blockDim.x + threadIdx.x; i < total;
         i += (long)gridDim.x*blockDim.x){
        int r = (int)(i/KE), k = (int)(i - (long)r*KE);
        float v = (k < EMBD) ? emb[(size_t)x[r]*EMBD + k] : 0.f;
        float hi = tf32_rna(v);
        g_xeh[i] = hi; g_xel[i] = tf32_rna(v - hi);
    }
}

// ---------------- x-part GEMM: [32768,304] x [304, 3x1024] (+bias) -----------
extern __shared__ char dynsm[];

__global__ void __launch_bounds__(256,1) k_xgemm(const float* __restrict__ br,
        const float* __restrict__ bu, const float* __restrict__ bc){
    float acc[2][2][4];
    const int m0  = blockIdx.x*64;
    const int n0g = blockIdx.y*64;
    const int g   = n0g >> 10;
    const int n0  = n0g & 1023;
    gemm32<2>(dynsm, g_xeh, g_xel, KE,
              g_Wxh + (size_t)g*HID*KE, g_Wxl + (size_t)g*HID*KE, KE,
              m0, n0, KE, acc);
    const float* bias = (g==0)?br:((g==1)?bu:bc);
    float* Xg = g_X + (size_t)g*SEQ*BATCH*HID;
    const int lane = threadIdx.x&31, warp = threadIdx.x>>5;
    const int wm = warp>>2, wn = warp&3;
    #pragma unroll
    for (int mt=0;mt<2;mt++)
      #pragma unroll
      for (int nt=0;nt<2;nt++)
        #pragma unroll
        for (int ep=0;ep<2;ep++){
            const int r = m0 + wm*32 + mt*16 + (lane>>2) + ep*8;
            const int c = n0 + wn*16 + nt*8 + (lane&3)*2;
            const int b = r>>7, t = r&127;
            float2 o;
            o.x = acc[mt][nt][ep*2+0] + bias[c];
            o.y = acc[mt][nt][ep*2+1] + bias[c+1];
            *(float2*)(Xg + ((size_t)t*BATCH + b)*HID + c) = o;
        }
}

// ---------------- persistent recurrence ----------------
__global__ void __launch_bounds__(256,1) k_recur(float* __restrict__ out,
                                                 const float* __restrict__ Wp){
    char*  sm  = dynsm;
    float* Wps = (float*)(dynsm + 61440);           // 20 x 64
    float* Cs  = (float*)(dynsm + 61440 + 5120);    // 32 x 65
    const int cta = blockIdx.x;
    const int tid = threadIdx.x, lane = tid&31, warp = tid>>5;
    const int wm = warp>>2, wn = warp&3;

    const int mA = (cta&3)*64,  nA = (cta>>2)*64;   // 256x2048 as 4x32 tiles
    const int mB = (cta&7)*32,  nB = (cta>>3)*64;   // 256x1024 as 8x16 tiles

    for (int i = tid; i < OUTD*64; i += 256){
        int o = i>>6, hh = i&63;
        Wps[o*64+hh] = Wp[(size_t)o*HID + nB + hh];
    }

    unsigned nbar = 0;
    for (int t=0; t<SEQ; ++t){
        // ---- phase A: r,u gates ----
        {
            float acc[2][2][4];
            gemm32<2>(sm, g_Ch, g_Cl, HID, g_Wruh, g_Wrul, HID, mA, nA, HID, acc);
            const bool isU = (nA >= HID);
            const float* Xg = g_X + (size_t)((isU?1:0)*SEQ + t)*BATCH*HID;
            #pragma unroll
            for (int mt=0;mt<2;mt++)
              #pragma unroll
              for (int nt=0;nt<2;nt++)
                #pragma unroll
                for (int ep=0;ep<2;ep++){
                    const int b = mA + wm*32 + mt*16 + (lane>>2) + ep*8;
                    const int c = nA + wn*16 + nt*8 + (lane&3)*2;
                    const int h = c & (HID-1);
                    const size_t idx = (size_t)b*HID + h;
                    float2 xv = *(const float2*)(Xg + idx);
                    float s0 = 1.f/(1.f+__expf(-(acc[mt][nt][ep*2+0] + xv.x)));
                    float s1 = 1.f/(1.f+__expf(-(acc[mt][nt][ep*2+1] + xv.y)));
                    if (isU){
                        __stcg((float2*)(g_u+idx), make_float2(s0,s1));
                    } else {
                        float2 cp = __ldcg((const float2*)(g_c32+idx));
                        float r0 = s0*cp.x, r1 = s1*cp.y;
                        float h0 = tf32_rna(r0), l0 = tf32_rna(r0-h0);
                        float h1 = tf32_rna(r1), l1 = tf32_rna(r1-h1);
                        __stcg((float2*)(g_RCh+idx), make_float2(h0,h1));
                        __stcg((float2*)(g_RCl+idx), make_float2(l0,l1));
                    }
                }
        }
        gridbar(nbar);
        // ---- phase B: candidate + state update + y ----
        {
            float acc[1][2][4];
            gemm32<1>(sm, g_RCh, g_RCl, HID, g_Wch, g_Wcl, HID, mB, nB, HID, acc);
            const float* Xg = g_X + (size_t)(2*SEQ + t)*BATCH*HID;
            #pragma unroll
            for (int nt=0;nt<2;nt++)
              #pragma unroll
              for (int ep=0;ep<2;ep++){
                  const int b = mB + wm*16 + (lane>>2) + ep*8;
                  const int c = nB + wn*16 + nt*8 + (lane&3)*2;
                  const size_t idx = (size_t)b*HID + c;
                  float2 xv = *(const float2*)(Xg + idx);
                  float2 uv = __ldcg((const float2*)(g_u+idx));
                  float2 cp = __ldcg((const float2*)(g_c32+idx));
                  float cc0 = tanhf(acc[0][nt][ep*2+0] + xv.x);
                  float cc1 = tanhf(acc[0][nt][ep*2+1] + xv.y);
                  float cn0 = uv.x*cc0 + (1.f-uv.x)*cp.x;
                  float cn1 = uv.y*cc1 + (1.f-uv.y)*cp.y;
                  __stcg((float2*)(g_c32+idx), make_float2(cn0,cn1));
                  float h0 = tf32_rna(cn0), l0 = tf32_rna(cn0-h0);
                  float h1 = tf32_rna(cn1), l1 = tf32_rna(cn1-h1);
                  __stcg((float2*)(g_Ch+idx), make_float2(h0,h1));
                  __stcg((float2*)(g_Cl+idx), make_float2(l0,l1));
                  Cs[(b-mB)*65 + (c-nB)  ] = cn0;
                  Cs[(b-mB)*65 + (c-nB)+1] = cn1;
              }
            __syncthreads();
            const int bl = tid & 31, og = tid >> 5;
            #pragma unroll
            for (int j=og; j<OUTD; j+=8){
                float s = 0.f;
                #pragma unroll 16
                for (int hh=0; hh<64; ++hh)
                    s += Cs[bl*65+hh] * Wps[j*64+hh];
                atomicAdd(&out[((size_t)(mB+bl)*SEQ + t)*OUTD + j], s);
            }
        }
        gridbar(nbar);
    }
}

// ---------------- launch ----------------
extern "C" void kernel_launch(void* const* d_in, const int* in_sizes, int n_in,
                              void* d_out, int out_size){
    const int*   x   = (const int*)  d_in[0];
    const float* emb = (const float*)d_in[1];
    const float* Wr  = (const float*)d_in[2];
    const float* br  = (const float*)d_in[3];
    const float* Wu  = (const float*)d_in[4];
    const float* bu  = (const float*)d_in[5];
    const float* Wc  = (const float*)d_in[6];
    const float* bc  = (const float*)d_in[7];
    const float* Wp  = (const float*)d_in[8];
    const float* bp  = (const float*)d_in[9];
    float* out = (float*)d_out;
    (void)in_sizes; (void)n_in; (void)out_size;

    static int attr_done = 0;
    if (!attr_done){
        cudaFuncSetAttribute(k_xgemm, cudaFuncAttributeMaxDynamicSharedMemorySize, 61440);
        cudaFuncSetAttribute(k_recur, cudaFuncAttributeMaxDynamicSharedMemorySize, 75264);
        attr_done = 1;
    }

    k_init<<<512, 256>>>(out, bp);
    k_prep<<<1024, 256>>>(Wr, Wu, Wc);
    k_gather<<<2048, 256>>>(x, emb);
    k_xgemm<<<dim3(512,48), 256, 61440>>>(br, bu, bc);
    k_recur<<<PCTA, 256, 75264>>>(out, Wp);
}

// round 6
// speedup vs baseline: 4.1512x; 1.4606x over previous
#include <cuda_runtime.h>
#include <cuda_fp16.h>
#include <cstdint>

#define BATCH 256
#define SEQ   128
#define HID   1024
#define EMBD  300
#define OUTD  20
#define CAT   1324
#define KE    304
#define KEP   152      // packed uints per row (KE/2)
#define HP    512      // packed uints per HID row
#define NROWS 32768
#define PCTA  128

// ---------------- static device scratch ----------------
// packed fp16 pairs along k: uint32 = (elem 2j in low16, elem 2j+1 in high16)
__device__ float    g_c32[BATCH*HID];                     // full-precision cell state
__device__ unsigned g_Chp [BATCH*HID/2], g_Clp [BATCH*HID/2];   // c  hi / scaled-lo
__device__ unsigned g_RChp[BATCH*HID/2], g_RClp[BATCH*HID/2];   // r*c
__device__ float    g_u  [BATCH*HID];
__device__ float    g_X  [3L*SEQ*BATCH*HID];              // x-part preacts (+bias)
__device__ unsigned g_Wruhp[2048L*HP], g_Wrulp[2048L*HP];
__device__ unsigned g_Wchp [1024L*HP], g_Wclp [1024L*HP];
__device__ unsigned g_Wxhp [3L*HID*KEP], g_Wxlp[3L*HID*KEP];
__device__ unsigned g_xehp [(long)NROWS*KEP], g_xelp[(long)NROWS*KEP];
__device__ unsigned g_barcnt;

#define LSCALE 2048.0f
#define LINV   (1.0f/2048.0f)

// ---------------- helpers ----------------
__device__ __forceinline__ unsigned packh2(float a, float b){
    __half2 h = __floats2half2_rn(a, b);
    return *reinterpret_cast<unsigned*>(&h);
}
__device__ __forceinline__ void split_pair(float v0, float v1, unsigned& hi, unsigned& lo){
    float h0 = __half2float(__float2half_rn(v0));
    float h1 = __half2float(__float2half_rn(v1));
    hi = packh2(h0, h1);
    lo = packh2((v0 - h0)*LSCALE, (v1 - h1)*LSCALE);
}
__device__ __forceinline__ void mma_f16(float c[4], const unsigned a[4], const unsigned b[2]){
    asm volatile("mma.sync.aligned.m16n8k16.row.col.f32.f16.f16.f32 "
        "{%0,%1,%2,%3},{%4,%5,%6,%7},{%8,%9},{%0,%1,%2,%3};"
        : "+f"(c[0]),"+f"(c[1]),"+f"(c[2]),"+f"(c[3])
        : "r"(a[0]),"r"(a[1]),"r"(a[2]),"r"(a[3]),"r"(b[0]),"r"(b[1]));
}
__device__ __forceinline__ void cp16(uint32_t d, const void* s){
    asm volatile("cp.async.cg.shared.global [%0], [%1], 16;" :: "r"(d), "l"(s));
}
#define CP_COMMIT asm volatile("cp.async.commit_group;")
#define CP_WAIT1  asm volatile("cp.async.wait_group 1;")

#define SU 12   // smem row stride in uints: 8 data + 4 pad -> all 32 frag lanes distinct banks

// ---------------- GEMM core: (MT*32) x 64 tile, K chunks of 16, 8 warps 2x4 ----
// C[m,n] = sum_k A[m,k]*B[n,k]; operands pre-split fp16 hi / scaled-lo, packed
// pairwise along k. accH = hi*hi sums; accM = (lo*hi + hi*lo) sums (scaled 2^11).
// 3-stage cp.async pipeline. ldp/ldbp in packed uints per row.
template<int MT>
__device__ void gemm16(char* sm,
    const unsigned* __restrict__ Ah, const unsigned* __restrict__ Al, int ldp,
    const unsigned* __restrict__ Bh, const unsigned* __restrict__ Bl, int ldbp,
    int m0, int n0, int K, float accH[MT][2][4], float accM[MT][2][4])
{
    constexpr int AR  = MT*32;
    constexpr int OAL = AR*SU;
    constexpr int OBH = 2*AR*SU;
    constexpr int OBL = OBH + 64*SU;
    constexpr int STG = OBL + 64*SU;      // uints per stage
    const int tid = threadIdx.x, lane = tid&31, warp = tid>>5;
    const int wm = warp>>2, wn = warp&3;
    const int lr = lane>>2, lc = lane&3;
    uint32_t smb = (uint32_t)__cvta_generic_to_shared(sm);
    const unsigned* smu = (const unsigned*)sm;

    #pragma unroll
    for (int i=0;i<MT;i++)
      #pragma unroll
      for (int j=0;j<2;j++)
        #pragma unroll
        for (int e=0;e<4;e++){ accH[i][j][e]=0.f; accM[i][j][e]=0.f; }

    auto fill = [&](int ki, int buf){
        const int kk = ki*8;                      // packed-k offset
        const uint32_t pb = smb + (uint32_t)buf*STG*4;
        for (int idx = tid; idx < AR*2; idx += 256){
            int r = idx>>1, c = idx&1;
            size_t off = (size_t)(m0+r)*ldp + kk + c*4;
            cp16(pb + (uint32_t)(r*SU + c*4)*4,        Ah + off);
            cp16(pb + (uint32_t)(OAL + r*SU + c*4)*4,  Al + off);
        }
        for (int idx = tid; idx < 64*2; idx += 256){
            int r = idx>>1, c = idx&1;
            size_t off = (size_t)(n0+r)*ldbp + kk + c*4;
            cp16(pb + (uint32_t)(OBH + r*SU + c*4)*4,  Bh + off);
            cp16(pb + (uint32_t)(OBL + r*SU + c*4)*4,  Bl + off);
        }
    };

    const int nk = K/16;
    fill(0,0); CP_COMMIT;
    fill(1,1); CP_COMMIT;

    for (int i=0;i<nk;i++){
        CP_WAIT1;
        __syncthreads();
        if (i+2 < nk) fill(i+2, (i+2)%3);
        CP_COMMIT;
        const unsigned* p = smu + (i%3)*STG;
        unsigned ah[MT][4], al[MT][4], bh[2][2], bl[2][2];
        #pragma unroll
        for (int mt=0; mt<MT; mt++){
            const int R = wm*MT*16 + mt*16;
            ah[mt][0] = p[(R+lr)*SU   + lc];
            ah[mt][1] = p[(R+8+lr)*SU + lc];
            ah[mt][2] = p[(R+lr)*SU   + 4+lc];
            ah[mt][3] = p[(R+8+lr)*SU + 4+lc];
            al[mt][0] = p[OAL + (R+lr)*SU   + lc];
            al[mt][1] = p[OAL + (R+8+lr)*SU + lc];
            al[mt][2] = p[OAL + (R+lr)*SU   + 4+lc];
            al[mt][3] = p[OAL + (R+8+lr)*SU + 4+lc];
        }
        #pragma unroll
        for (int nt=0; nt<2; nt++){
            const int N = wn*16 + nt*8;
            bh[nt][0] = p[OBH + (N+lr)*SU + lc];
            bh[nt][1] = p[OBH + (N+lr)*SU + 4+lc];
            bl[nt][0] = p[OBL + (N+lr)*SU + lc];
            bl[nt][1] = p[OBL + (N+lr)*SU + 4+lc];
        }
        #pragma unroll
        for (int mt=0; mt<MT; mt++)
          #pragma unroll
          for (int nt=0; nt<2; nt++){
              mma_f16(accH[mt][nt], ah[mt], bh[nt]);   // hi*hi
              mma_f16(accM[mt][nt], al[mt], bh[nt]);   // lo*hi (scaled)
              mma_f16(accM[mt][nt], ah[mt], bl[nt]);   // hi*lo (scaled)
          }
    }
    __syncthreads();   // smem safe for reuse after return
}

// ---------------- grid barrier (release/acquire, monotonic counter) -----------
__device__ __forceinline__ void gridbar(unsigned& nbar){
    __threadfence();
    __syncthreads();
    ++nbar;
    if (threadIdx.x == 0){
        asm volatile("red.release.gpu.global.add.u32 [%0], 1;" :: "l"(&g_barcnt) : "memory");
        const unsigned target = (unsigned)PCTA * nbar;
        unsigned v;
        do {
            asm volatile("ld.acquire.gpu.global.u32 %0, [%1];" : "=r"(v) : "l"(&g_barcnt) : "memory");
        } while (v < target);
    }
    __syncthreads();
}

// ---------------- prep kernels ----------------
__global__ void k_init(float* __restrict__ out, const float* __restrict__ bp){
    const long nout = (long)BATCH*SEQ*OUTD;
    for (long i = blockIdx.x*(long)blockDim.x + threadIdx.x; i < nout;
         i += (long)gridDim.x*blockDim.x){
        out[i] = bp[i % OUTD];
        if (i < (long)BATCH*HID) g_c32[i] = 0.f;
        if (i < (long)BATCH*HID/2){ g_Chp[i] = 0u; g_Clp[i] = 0u; }
        if (i == 0) g_barcnt = 0u;
    }
}

__global__ void k_prep(const float* __restrict__ Wr, const float* __restrict__ Wu,
                       const float* __restrict__ Wc){
    const long N1 = 2048L*HP, N2 = 1024L*HP, N3 = 3L*HID*KEP;
    for (long i = blockIdx.x*(long)blockDim.x + threadIdx.x; i < N1+N2+N3;
         i += (long)gridDim.x*blockDim.x){
        float v0, v1; unsigned *dh, *dl; long j;
        if (i < N1){
            j = i; int n = (int)(j/HP), kp = (int)(j - (long)n*HP);
            const float* W = (n < 1024) ? Wr : Wu;
            int nn = (n < 1024) ? n : n-1024;
            v0 = W[(long)nn*CAT + 2*kp];
            v1 = W[(long)nn*CAT + 2*kp+1];
            dh = g_Wruhp; dl = g_Wrulp;
        } else if (i < N1+N2){
            j = i - N1; int n = (int)(j/HP), kp = (int)(j - (long)n*HP);
            v0 = Wc[(long)n*CAT + 2*kp];
            v1 = Wc[(long)n*CAT + 2*kp+1];
            dh = g_Wchp; dl = g_Wclp;
        } else {
            j = i - N1 - N2; int n = (int)(j/KEP), kp = (int)(j - (long)n*KEP);
            int g = n / HID, h = n - g*HID;
            const float* W = (g==0)?Wr:((g==1)?Wu:Wc);
            int k0 = 2*kp, k1 = 2*kp+1;
            v0 = (k0 < EMBD) ? W[(long)h*CAT + HID + k0] : 0.f;
            v1 = (k1 < EMBD) ? W[(long)h*CAT + HID + k1] : 0.f;
            dh = g_Wxhp; dl = g_Wxlp;
        }
        unsigned hi, lo; split_pair(v0, v1, hi, lo);
        dh[j] = hi; dl[j] = lo;
    }
}

__global__ void k_gather(const int* __restrict__ x, const float* __restrict__ emb){
    const long total = (long)NROWS*KEP;
    for (long i = blockIdx.x*(long)blockDim.x + threadIdx.x; i < total;
         i += (long)gridDim.x*blockDim.x){
        int r = (int)(i/KEP), kp = (int)(i - (long)r*KEP);
        int k0 = 2*kp, k1 = 2*kp+1;
        const float* er = emb + (size_t)x[r]*EMBD;
        float v0 = (k0 < EMBD) ? er[k0] : 0.f;
        float v1 = (k1 < EMBD) ? er[k1] : 0.f;
        unsigned hi, lo; split_pair(v0, v1, hi, lo);
        g_xehp[i] = hi; g_xelp[i] = lo;
    }
}

// ---------------- x-part GEMM: [32768,304] x [304, 3x1024] (+bias) -----------
extern __shared__ char dynsm[];

__global__ void __launch_bounds__(256,1) k_xgemm(const float* __restrict__ br,
        const float* __restrict__ bu, const float* __restrict__ bc){
    float accH[2][2][4], accM[2][2][4];
    const int m0  = blockIdx.x*64;
    const int n0g = blockIdx.y*64;
    const int g   = n0g >> 10;
    const int n0  = n0g & 1023;
    gemm16<2>(dynsm, g_xehp, g_xelp, KEP,
              g_Wxhp + (size_t)g*HID*KEP, g_Wxlp + (size_t)g*HID*KEP, KEP,
              m0, n0, KE, accH, accM);
    const float* bias = (g==0)?br:((g==1)?bu:bc);
    float* Xg = g_X + (size_t)g*SEQ*BATCH*HID;
    const int lane = threadIdx.x&31, warp = threadIdx.x>>5;
    const int wm = warp>>2, wn = warp&3;
    #pragma unroll
    for (int mt=0;mt<2;mt++)
      #pragma unroll
      for (int nt=0;nt<2;nt++)
        #pragma unroll
        for (int ep=0;ep<2;ep++){
            const int r = m0 + wm*32 + mt*16 + (lane>>2) + ep*8;
            const int c = n0 + wn*16 + nt*8 + (lane&3)*2;
            const int b = r>>7, t = r&127;
            float2 o;
            o.x = accH[mt][nt][ep*2+0] + accM[mt][nt][ep*2+0]*LINV + bias[c];
            o.y = accH[mt][nt][ep*2+1] + accM[mt][nt][ep*2+1]*LINV + bias[c+1];
            *(float2*)(Xg + ((size_t)t*BATCH + b)*HID + c) = o;
        }
}

// ---------------- persistent recurrence ----------------
__global__ void __launch_bounds__(256,1) k_recur(float* __restrict__ out,
                                                 const float* __restrict__ Wp){
    char*  sm  = dynsm;
    float* Wps = (float*)(dynsm + 36864);           // 20 x 64
    float* Cs  = (float*)(dynsm + 36864 + 5120);    // 32 x 65
    const int cta = blockIdx.x;
    const int tid = threadIdx.x, lane = tid&31, warp = tid>>5;
    const int wm = warp>>2, wn = warp&3;

    const int mA = (cta&3)*64,  nA = (cta>>2)*64;   // 256x2048 as 4x32 tiles
    const int mB = (cta&7)*32,  nB = (cta>>3)*64;   // 256x1024 as 8x16 tiles

    for (int i = tid; i < OUTD*64; i += 256){
        int o = i>>6, hh = i&63;
        Wps[o*64+hh] = Wp[(size_t)o*HID + nB + hh];
    }

    unsigned nbar = 0;
    for (int t=0; t<SEQ; ++t){
        // ---- phase A: r,u gates ----
        {
            float accH[2][2][4], accM[2][2][4];
            gemm16<2>(sm, g_Chp, g_Clp, HP, g_Wruhp, g_Wrulp, HP, mA, nA, HID, accH, accM);
            const bool isU = (nA >= HID);
            const float* Xg = g_X + (size_t)((isU?1:0)*SEQ + t)*BATCH*HID;
            #pragma unroll
            for (int mt=0;mt<2;mt++)
              #pragma unroll
              for (int nt=0;nt<2;nt++)
                #pragma unroll
                for (int ep=0;ep<2;ep++){
                    const int b = mA + wm*32 + mt*16 + (lane>>2) + ep*8;
                    const int c = nA + wn*16 + nt*8 + (lane&3)*2;
                    const int h = c & (HID-1);
                    const size_t idx = (size_t)b*HID + h;
                    float2 xv = *(const float2*)(Xg + idx);
                    float p0 = accH[mt][nt][ep*2+0] + accM[mt][nt][ep*2+0]*LINV + xv.x;
                    float p1 = accH[mt][nt][ep*2+1] + accM[mt][nt][ep*2+1]*LINV + xv.y;
                    float s0 = 1.f/(1.f+__expf(-p0));
                    float s1 = 1.f/(1.f+__expf(-p1));
                    if (isU){
                        __stcg((float2*)(g_u+idx), make_float2(s0,s1));
                    } else {
                        float2 cp = __ldcg((const float2*)(g_c32+idx));
                        unsigned hi, lo; split_pair(s0*cp.x, s1*cp.y, hi, lo);
                        __stcg(&g_RChp[idx>>1], hi);
                        __stcg(&g_RClp[idx>>1], lo);
                    }
                }
        }
        gridbar(nbar);
        // ---- phase B: candidate + state update + y ----
        {
            float accH[1][2][4], accM[1][2][4];
            gemm16<1>(sm, g_RChp, g_RClp, HP, g_Wchp, g_Wclp, HP, mB, nB, HID, accH, accM);
            const float* Xg = g_X + (size_t)(2*SEQ + t)*BATCH*HID;
            #pragma unroll
            for (int nt=0;nt<2;nt++)
              #pragma unroll
              for (int ep=0;ep<2;ep++){
                  const int b = mB + wm*16 + (lane>>2) + ep*8;
                  const int c = nB + wn*16 + nt*8 + (lane&3)*2;
                  const size_t idx = (size_t)b*HID + c;
                  float2 xv = *(const float2*)(Xg + idx);
                  float2 uv = __ldcg((const float2*)(g_u+idx));
                  float2 cp = __ldcg((const float2*)(g_c32+idx));
                  float cc0 = tanhf(accH[0][nt][ep*2+0] + accM[0][nt][ep*2+0]*LINV + xv.x);
                  float cc1 = tanhf(accH[0][nt][ep*2+1] + accM[0][nt][ep*2+1]*LINV + xv.y);
                  float cn0 = uv.x*cc0 + (1.f-uv.x)*cp.x;
                  float cn1 = uv.y*cc1 + (1.f-uv.y)*cp.y;
                  __stcg((float2*)(g_c32+idx), make_float2(cn0,cn1));
                  unsigned hi, lo; split_pair(cn0, cn1, hi, lo);
                  __stcg(&g_Chp[idx>>1], hi);
                  __stcg(&g_Clp[idx>>1], lo);
                  Cs[(b-mB)*65 + (c-nB)  ] = cn0;
                  Cs[(b-mB)*65 + (c-nB)+1] = cn1;
              }
            __syncthreads();
            const int bl = tid & 31, og = tid >> 5;
            #pragma unroll
            for (int j=og; j<OUTD; j+=8){
                float s = 0.f;
                #pragma unroll 16
                for (int hh=0; hh<64; ++hh)
                    s += Cs[bl*65+hh] * Wps[j*64+hh];
                atomicAdd(&out[((size_t)(mB+bl)*SEQ + t)*OUTD + j], s);
            }
        }
        gridbar(nbar);
    }
}

// ---------------- launch ----------------
extern "C" void kernel_launch(void* const* d_in, const int* in_sizes, int n_in,
                              void* d_out, int out_size){
    const int*   x   = (const int*)  d_in[0];
    const float* emb = (const float*)d_in[1];
    const float* Wr  = (const float*)d_in[2];
    const float* br  = (const float*)d_in[3];
    const float* Wu  = (const float*)d_in[4];
    const float* bu  = (const float*)d_in[5];
    const float* Wc  = (const float*)d_in[6];
    const float* bc  = (const float*)d_in[7];
    const float* Wp  = (const float*)d_in[8];
    const float* bp  = (const float*)d_in[9];
    float* out = (float*)d_out;
    (void)in_sizes; (void)n_in; (void)out_size;

    static int attr_done = 0;
    if (!attr_done){
        cudaFuncSetAttribute(k_xgemm, cudaFuncAttributeMaxDynamicSharedMemorySize, 36864);
        cudaFuncSetAttribute(k_recur, cudaFuncAttributeMaxDynamicSharedMemorySize, 50304);
        attr_done = 1;
    }

    k_init<<<512, 256>>>(out, bp);
    k_prep<<<1024, 256>>>(Wr, Wu, Wc);
    k_gather<<<2048, 256>>>(x, emb);
    k_xgemm<<<dim3(512,48), 256, 36864>>>(br, bu, bc);
    k_recur<<<PCTA, 256, 50304>>>(out, Wp);
}

// round 8
// speedup vs baseline: 4.9201x; 1.1852x over previous
#include <cuda_runtime.h>
#include <cuda_fp16.h>
#include <cstdint>

#define BATCH 256
#define SEQ   128
#define HID   1024
#define EMBD  300
#define OUTD  20
#define CAT   1324
#define KE    320
#define KEP   160      // packed uints per row (KE/2)
#define HP    512      // packed uints per HID row
#define NROWS 32768
#define PCTA  128

// ---------------- static device scratch ----------------
// packed fp16 pairs along k: uint32 = (elem 2j low16, elem 2j+1 high16)
__device__ float    g_c32[BATCH*HID];
__device__ unsigned g_Chp [BATCH*HID/2], g_Clp [BATCH*HID/2];
__device__ unsigned g_RChp[BATCH*HID/2], g_RClp[BATCH*HID/2];
__device__ float    g_u  [BATCH*HID];
__device__ float    g_X  [3L*SEQ*BATCH*HID];
__device__ unsigned g_Wruhp[2048L*HP], g_Wrulp[2048L*HP];
__device__ unsigned g_Wchp [1024L*HP], g_Wclp [1024L*HP];
__device__ unsigned g_Wxhp [3L*HID*KEP], g_Wxlp[3L*HID*KEP];
__device__ unsigned g_xehp [(long)NROWS*KEP], g_xelp[(long)NROWS*KEP];
__device__ unsigned g_barcnt;

#define LSCALE 2048.0f
#define LINV   (1.0f/2048.0f)

// ---------------- helpers ----------------
__device__ __forceinline__ unsigned packh2(float a, float b){
    __half2 h = __floats2half2_rn(a, b);
    return *reinterpret_cast<unsigned*>(&h);
}
__device__ __forceinline__ void split_pair(float v0, float v1, unsigned& hi, unsigned& lo){
    float h0 = __half2float(__float2half_rn(v0));
    float h1 = __half2float(__float2half_rn(v1));
    hi = packh2(h0, h1);
    lo = packh2((v0 - h0)*LSCALE, (v1 - h1)*LSCALE);
}
__device__ __forceinline__ void mma_f16(float c[4], const unsigned a[4], const unsigned b[2]){
    asm volatile("mma.sync.aligned.m16n8k16.row.col.f32.f16.f16.f32 "
        "{%0,%1,%2,%3},{%4,%5,%6,%7},{%8,%9},{%0,%1,%2,%3};"
        : "+f"(c[0]),"+f"(c[1]),"+f"(c[2]),"+f"(c[3])
        : "r"(a[0]),"r"(a[1]),"r"(a[2]),"r"(a[3]),"r"(b[0]),"r"(b[1]));
}
__device__ __forceinline__ void cp16(uint32_t d, const void* s){
    asm volatile("cp.async.cg.shared.global [%0], [%1], 16;" :: "r"(d), "l"(s));
}
#define CP_COMMIT asm volatile("cp.async.commit_group;")
#define CP_WAIT1  asm volatile("cp.async.wait_group 1;")

#define ST 20   // smem row stride in uints: 16 data + 4 pad -> conflict-free frag LDS

// ---------------- GEMM core: (MT*32) x 64 tile, K chunks of 32, 8 warps 2x4 ----
// C[m,n] = sum_k A[m,k]*B[n,k]; operands fp16 hi / scaled-lo, packed pairs on k.
// accH = hi*hi; accM = lo*hi + hi*lo (scaled 2^11). 3-stage cp.async pipeline,
// one __syncthreads per 32-k, all fragments batched before MMA passes.
template<int MT>
__device__ __forceinline__ void gemm16(char* sm,
    const unsigned* __restrict__ Ah, const unsigned* __restrict__ Al, int ldp,
    const unsigned* __restrict__ Bh, const unsigned* __restrict__ Bl, int ldbp,
    int m0, int n0, int K, float accH[MT][2][4], float accM[MT][2][4])
{
    constexpr int AR  = MT*32;
    constexpr int OAL = AR*ST;
    constexpr int OBH = 2*AR*ST;
    constexpr int OBL = OBH + 64*ST;
    constexpr int STG = OBL + 64*ST;      // uints per stage
    const int tid = threadIdx.x, lane = tid&31, warp = tid>>5;
    const int wm = warp>>2, wn = warp&3;
    const int lr = lane>>2, lc = lane&3;
    uint32_t smb = (uint32_t)__cvta_generic_to_shared(sm);
    const unsigned* smu = (const unsigned*)sm;

    #pragma unroll
    for (int i=0;i<MT;i++)
      #pragma unroll
      for (int j=0;j<2;j++)
        #pragma unroll
        for (int e=0;e<4;e++){ accH[i][j][e]=0.f; accM[i][j][e]=0.f; }

    auto fill = [&](int ki, int buf){
        const int kk = ki*16;                     // packed-k uints per 32-k chunk
        const uint32_t pb = smb + (uint32_t)buf*STG*4;
        #pragma unroll
        for (int idx = tid; idx < AR*4; idx += 256){
            int r = idx>>2, c = idx&3;
            size_t off = (size_t)(m0+r)*ldp + kk + c*4;
            cp16(pb + (uint32_t)(r*ST + c*4)*4,        Ah + off);
            cp16(pb + (uint32_t)(OAL + r*ST + c*4)*4,  Al + off);
        }
        #pragma unroll
        for (int idx = tid; idx < 256; idx += 256){
            int r = idx>>2, c = idx&3;
            size_t off = (size_t)(n0+r)*ldbp + kk + c*4;
            cp16(pb + (uint32_t)(OBH + r*ST + c*4)*4,  Bh + off);
            cp16(pb + (uint32_t)(OBL + r*ST + c*4)*4,  Bl + off);
        }
    };

    const int nk = K/32;
    fill(0,0); CP_COMMIT;
    fill(1,1); CP_COMMIT;

    for (int i=0;i<nk;i++){
        CP_WAIT1;
        __syncthreads();
        if (i+2 < nk) fill(i+2, (i+2)%3);
        CP_COMMIT;
        const unsigned* p = smu + (i%3)*STG;
        unsigned ah[2][MT][4], al[2][MT][4], bh[2][2][2], bl[2][2][2];
        #pragma unroll
        for (int s=0;s<2;s++){
            const unsigned* q = p + s*8;
            #pragma unroll
            for (int mt=0; mt<MT; mt++){
                const int R = wm*MT*16 + mt*16;
                ah[s][mt][0] = q[(R+lr)*ST   + lc];
                ah[s][mt][1] = q[(R+8+lr)*ST + lc];
                ah[s][mt][2] = q[(R+lr)*ST   + 4+lc];
                ah[s][mt][3] = q[(R+8+lr)*ST + 4+lc];
                al[s][mt][0] = q[OAL + (R+lr)*ST   + lc];
                al[s][mt][1] = q[OAL + (R+8+lr)*ST + lc];
                al[s][mt][2] = q[OAL + (R+lr)*ST   + 4+lc];
                al[s][mt][3] = q[OAL + (R+8+lr)*ST + 4+lc];
            }
            #pragma unroll
            for (int nt=0; nt<2; nt++){
                const int N = wn*16 + nt*8;
                bh[s][nt][0] = q[OBH + (N+lr)*ST + lc];
                bh[s][nt][1] = q[OBH + (N+lr)*ST + 4+lc];
                bl[s][nt][0] = q[OBL + (N+lr)*ST + lc];
                bl[s][nt][1] = q[OBL + (N+lr)*ST + 4+lc];
            }
        }
        // 6 passes; dependent accM updates are >= 2 passes apart
        #pragma unroll
        for (int mt=0; mt<MT; mt++)
          #pragma unroll
          for (int nt=0; nt<2; nt++) mma_f16(accH[mt][nt], ah[0][mt], bh[0][nt]);
        #pragma unroll
        for (int mt=0; mt<MT; mt++)
          #pragma unroll
          for (int nt=0; nt<2; nt++) mma_f16(accM[mt][nt], al[0][mt], bh[0][nt]);
        #pragma unroll
        for (int mt=0; mt<MT; mt++)
          #pragma unroll
          for (int nt=0; nt<2; nt++) mma_f16(accH[mt][nt], ah[1][mt], bh[1][nt]);
        #pragma unroll
        for (int mt=0; mt<MT; mt++)
          #pragma unroll
          for (int nt=0; nt<2; nt++) mma_f16(accM[mt][nt], ah[0][mt], bl[0][nt]);
        #pragma unroll
        for (int mt=0; mt<MT; mt++)
          #pragma unroll
          for (int nt=0; nt<2; nt++) mma_f16(accM[mt][nt], al[1][mt], bh[1][nt]);
        #pragma unroll
        for (int mt=0; mt<MT; mt++)
          #pragma unroll
          for (int nt=0; nt<2; nt++) mma_f16(accM[mt][nt], ah[1][mt], bl[1][nt]);
    }
    __syncthreads();
}

// ---------------- grid barrier (release/acquire, monotonic counter) -----------
__device__ __forceinline__ void gridbar(unsigned& nbar){
    __threadfence();
    __syncthreads();
    ++nbar;
    if (threadIdx.x == 0){
        asm volatile("red.release.gpu.global.add.u32 [%0], 1;" :: "l"(&g_barcnt) : "memory");
        const unsigned target = (unsigned)PCTA * nbar;
        unsigned v;
        do {
            asm volatile("ld.acquire.gpu.global.u32 %0, [%1];" : "=r"(v) : "l"(&g_barcnt) : "memory");
        } while (v < target);
    }
    __syncthreads();
}

// ---------------- prep kernels ----------------
__global__ void k_init(float* __restrict__ out, const float* __restrict__ bp){
    const long nout = (long)BATCH*SEQ*OUTD;
    for (long i = blockIdx.x*(long)blockDim.x + threadIdx.x; i < nout;
         i += (long)gridDim.x*blockDim.x){
        out[i] = bp[i % OUTD];
        if (i < (long)BATCH*HID) g_c32[i] = 0.f;
        if (i < (long)BATCH*HID/2){ g_Chp[i] = 0u; g_Clp[i] = 0u; }
        if (i == 0) g_barcnt = 0u;
    }
}

__global__ void k_prep(const float* __restrict__ Wr, const float* __restrict__ Wu,
                       const float* __restrict__ Wc){
    const long N1 = 2048L*HP, N2 = 1024L*HP, N3 = 3L*HID*KEP;
    for (long i = blockIdx.x*(long)blockDim.x + threadIdx.x; i < N1+N2+N3;
         i += (long)gridDim.x*blockDim.x){
        float v0, v1; unsigned *dh, *dl; long j;
        if (i < N1){
            j = i; int n = (int)(j/HP), kp = (int)(j - (long)n*HP);
            const float* W = (n < 1024) ? Wr : Wu;
            int nn = (n < 1024) ? n : n-1024;
            v0 = W[(long)nn*CAT + 2*kp];
            v1 = W[(long)nn*CAT + 2*kp+1];
            dh = g_Wruhp; dl = g_Wrulp;
        } else if (i < N1+N2){
            j = i - N1; int n = (int)(j/HP), kp = (int)(j - (long)n*HP);
            v0 = Wc[(long)n*CAT + 2*kp];
            v1 = Wc[(long)n*CAT + 2*kp+1];
            dh = g_Wchp; dl = g_Wclp;
        } else {
            j = i - N1 - N2; int n = (int)(j/KEP), kp = (int)(j - (long)n*KEP);
            int g = n / HID, h = n - g*HID;
            const float* W = (g==0)?Wr:((g==1)?Wu:Wc);
            int k0 = 2*kp, k1 = 2*kp+1;
            v0 = (k0 < EMBD) ? W[(long)h*CAT + HID + k0] : 0.f;
            v1 = (k1 < EMBD) ? W[(long)h*CAT + HID + k1] : 0.f;
            dh = g_Wxhp; dl = g_Wxlp;
        }
        unsigned hi, lo; split_pair(v0, v1, hi, lo);
        dh[j] = hi; dl[j] = lo;
    }
}

__global__ void k_gather(const int* __restrict__ x, const float* __restrict__ emb){
    const long total = (long)NROWS*KEP;
    for (long i = blockIdx.x*(long)blockDim.x + threadIdx.x; i < total;
         i += (long)gridDim.x*blockDim.x){
        int r = (int)(i/KEP), kp = (int)(i - (long)r*KEP);
        int k0 = 2*kp, k1 = 2*kp+1;
        const float* er = emb + (size_t)x[r]*EMBD;
        float v0 = (k0 < EMBD) ? er[k0] : 0.f;
        float v1 = (k1 < EMBD) ? er[k1] : 0.f;
        unsigned hi, lo; split_pair(v0, v1, hi, lo);
        g_xehp[i] = hi; g_xelp[i] = lo;
    }
}

// ---------------- x-part GEMM: [32768,320] x [320, 3x1024] (+bias) -----------
extern __shared__ char dynsm[];

__global__ void __launch_bounds__(256,1) k_xgemm(const float* __restrict__ br,
        const float* __restrict__ bu, const float* __restrict__ bc){
    float accH[2][2][4], accM[2][2][4];
    const int m0  = blockIdx.x*64;
    const int n0g = blockIdx.y*64;
    const int g   = n0g >> 10;
    const int n0  = n0g & 1023;
    gemm16<2>(dynsm, g_xehp, g_xelp, KEP,
              g_Wxhp + (size_t)g*HID*KEP, g_Wxlp + (size_t)g*HID*KEP, KEP,
              m0, n0, KE, accH, accM);
    const float* bias = (g==0)?br:((g==1)?bu:bc);
    float* Xg = g_X + (size_t)g*SEQ*BATCH*HID;
    const int lane = threadIdx.x&31, warp = threadIdx.x>>5;
    const int wm = warp>>2, wn = warp&3;
    #pragma unroll
    for (int mt=0;mt<2;mt++)
      #pragma unroll
      for (int nt=0;nt<2;nt++)
        #pragma unroll
        for (int ep=0;ep<2;ep++){
            const int r = m0 + wm*32 + mt*16 + (lane>>2) + ep*8;
            const int c = n0 + wn*16 + nt*8 + (lane&3)*2;
            const int b = r>>7, t = r&127;
            float2 o;
            o.x = accH[mt][nt][ep*2+0] + accM[mt][nt][ep*2+0]*LINV + bias[c];
            o.y = accH[mt][nt][ep*2+1] + accM[mt][nt][ep*2+1]*LINV + bias[c+1];
            *(float2*)(Xg + ((size_t)t*BATCH + b)*HID + c) = o;
        }
}

// ---------------- persistent recurrence ----------------
__global__ void __launch_bounds__(256,1) k_recur(float* __restrict__ out,
                                                 const float* __restrict__ Wp){
    char*  sm  = dynsm;
    float* Wps = (float*)(dynsm + 61440);           // 20 x 64
    float* Cs  = (float*)(dynsm + 61440 + 5120);    // 32 x 65
    const int cta = blockIdx.x;
    const int tid = threadIdx.x, lane = tid&31, warp = tid>>5;
    const int wm = warp>>2, wn = warp&3;

    const int mA = (cta&3)*64,  nA = (cta>>2)*64;   // 256x2048 as 4x32 tiles
    const int mB = (cta&7)*32,  nB = (cta>>3)*64;   // 256x1024 as 8x16 tiles

    for (int i = tid; i < OUTD*64; i += 256){
        int o = i>>6, hh = i&63;
        Wps[o*64+hh] = Wp[(size_t)o*HID + nB + hh];
    }

    unsigned nbar = 0;
    for (int t=0; t<SEQ; ++t){
        // ---- phase A: r,u gates ----
        {
            float accH[2][2][4], accM[2][2][4];
            gemm16<2>(sm, g_Chp, g_Clp, HP, g_Wruhp, g_Wrulp, HP, mA, nA, HID, accH, accM);
            const bool isU = (nA >= HID);
            const float* Xg = g_X + (size_t)((isU?1:0)*SEQ + t)*BATCH*HID;
            #pragma unroll
            for (int mt=0;mt<2;mt++)
              #pragma unroll
              for (int nt=0;nt<2;nt++)
                #pragma unroll
                for (int ep=0;ep<2;ep++){
                    const int b = mA + wm*32 + mt*16 + (lane>>2) + ep*8;
                    const int c = nA + wn*16 + nt*8 + (lane&3)*2;
                    const int h = c & (HID-1);
                    const size_t idx = (size_t)b*HID + h;
                    float2 xv = *(const float2*)(Xg + idx);
                    float p0 = accH[mt][nt][ep*2+0] + accM[mt][nt][ep*2+0]*LINV + xv.x;
                    float p1 = accH[mt][nt][ep*2+1] + accM[mt][nt][ep*2+1]*LINV + xv.y;
                    float s0 = 1.f/(1.f+__expf(-p0));
                    float s1 = 1.f/(1.f+__expf(-p1));
                    if (isU){
                        __stcg((float2*)(g_u+idx), make_float2(s0,s1));
                    } else {
                        float2 cp = __ldcg((const float2*)(g_c32+idx));
                        unsigned hi, lo; split_pair(s0*cp.x, s1*cp.y, hi, lo);
                        __stcg(&g_RChp[idx>>1], hi);
                        __stcg(&g_RClp[idx>>1], lo);
                    }
                }
        }
        gridbar(nbar);
        // ---- phase B: candidate + state update + y ----
        {
            float accH[1][2][4], accM[1][2][4];
            gemm16<1>(sm, g_RChp, g_RClp, HP, g_Wchp, g_Wclp, HP, mB, nB, HID, accH, accM);
            const float* Xg = g_X + (size_t)(2*SEQ + t)*BATCH*HID;
            #pragma unroll
            for (int nt=0;nt<2;nt++)
              #pragma unroll
              for (int ep=0;ep<2;ep++){
                  const int b = mB + wm*16 + (lane>>2) + ep*8;
                  const int c = nB + wn*16 + nt*8 + (lane&3)*2;
                  const size_t idx = (size_t)b*HID + c;
                  float2 xv = *(const float2*)(Xg + idx);
                  float2 uv = __ldcg((const float2*)(g_u+idx));
                  float2 cp = __ldcg((const float2*)(g_c32+idx));
                  float cc0 = tanhf(accH[0][nt][ep*2+0] + accM[0][nt][ep*2+0]*LINV + xv.x);
                  float cc1 = tanhf(accH[0][nt][ep*2+1] + accM[0][nt][ep*2+1]*LINV + xv.y);
                  float cn0 = uv.x*cc0 + (1.f-uv.x)*cp.x;
                  float cn1 = uv.y*cc1 + (1.f-uv.y)*cp.y;
                  __stcg((float2*)(g_c32+idx), make_float2(cn0,cn1));
                  unsigned hi, lo; split_pair(cn0, cn1, hi, lo);
                  __stcg(&g_Chp[idx>>1], hi);
                  __stcg(&g_Clp[idx>>1], lo);
                  Cs[(b-mB)*65 + (c-nB)  ] = cn0;
                  Cs[(b-mB)*65 + (c-nB)+1] = cn1;
              }
            __syncthreads();
            const int bl = tid & 31, og = tid >> 5;
            #pragma unroll
            for (int j=og; j<OUTD; j+=8){
                float s = 0.f;
                #pragma unroll 16
                for (int hh=0; hh<64; ++hh)
                    s += Cs[bl*65+hh] * Wps[j*64+hh];
                atomicAdd(&out[((size_t)(mB+bl)*SEQ + t)*OUTD + j], s);
            }
        }
        gridbar(nbar);
    }
}

// ---------------- launch ----------------
extern "C" void kernel_launch(void* const* d_in, const int* in_sizes, int n_in,
                              void* d_out, int out_size){
    const int*   x   = (const int*)  d_in[0];
    const float* emb = (const float*)d_in[1];
    const float* Wr  = (const float*)d_in[2];
    const float* br  = (const float*)d_in[3];
    const float* Wu  = (const float*)d_in[4];
    const float* bu  = (const float*)d_in[5];
    const float* Wc  = (const float*)d_in[6];
    const float* bc  = (const float*)d_in[7];
    const float* Wp  = (const float*)d_in[8];
    const float* bp  = (const float*)d_in[9];
    float* out = (float*)d_out;
    (void)in_sizes; (void)n_in; (void)out_size;

    static int attr_done = 0;
    if (!attr_done){
        cudaFuncSetAttribute(k_xgemm, cudaFuncAttributeMaxDynamicSharedMemorySize, 61440);
        cudaFuncSetAttribute(k_recur, cudaFuncAttributeMaxDynamicSharedMemorySize, 74880);
        attr_done = 1;
    }

    k_init<<<512, 256>>>(out, bp);
    k_prep<<<1024, 256>>>(Wr, Wu, Wc);
    k_gather<<<2048, 256>>>(x, emb);
    k_xgemm<<<dim3(512,48), 256, 61440>>>(br, bu, bc);
    k_recur<<<PCTA, 256, 74880>>>(out, Wp);
}